// round 15
// baseline (speedup 1.0000x reference)
#include <cuda_runtime.h>
#include <cuda_fp16.h>
#include <cstdint>

// ============================================================================
// Single-term fp16 mma.sync implicit-GEMM conv, round 15.
// Same math as R14 (D = ah*bh, A=w*64 fp16, B=x fp16, rel_err ~2.9e-4).
// NEW: B gather uses direct 4-byte cp.async (global->smem, no register
// staging, no STS), one commit group per chunk (A 2x16B + B 8x4B),
// 3-stage pipeline. k-major swizzled B smem + ldsm.trans as in R14.
// ============================================================================

#define KTOT   2304
#define KCH    72            // 2304 / 32
#define NPIMG  2916
#define OUTIMG (512*NPIMG)
#define XIMG   (256*3136)
#define XN     (32*XIMG)     // 25690112 elements

#define A_TILE      8192     // A plane, 128 rows x 64B (swizzled, as R12)
#define STAGE_BYTES 16384    // A 8KB + B 8KB
#define OFF_B       8192
#define NSTAGE      3
#define OFF_KOFF    (NSTAGE*STAGE_BYTES)   // 49152
#define SMEM_BYTES  (OFF_KOFF + KTOT*4)    // 58368

// A (scaled x64, fp16) in swizzled smem-tile layout: [mt(4)][ch(72)][8KB]
__device__ __align__(16) unsigned char g_asplit[4ull*72*8192];    // 2.4MB
// x as fp16, plus copy shifted by one element: g_xh2[j] = x_fp16[j+1]
__device__ __align__(16) __half g_xh [XN];                        // 51.4MB
__device__ __align__(16) __half g_xh2[XN];                        // 51.4MB

// ---------------------------------------------------------------------------
__device__ __forceinline__ uint32_t smem_u32(const void* p) {
    uint32_t a;
    asm("{ .reg .u64 t; cvta.to.shared.u64 t, %1; cvt.u32.u64 %0, t; }"
        : "=r"(a) : "l"(p));
    return a;
}
__device__ __forceinline__ void ldsm4(uint32_t a, uint32_t& r0, uint32_t& r1,
                                      uint32_t& r2, uint32_t& r3) {
    asm volatile("ldmatrix.sync.aligned.m8n8.x4.shared.b16 {%0,%1,%2,%3}, [%4];"
                 : "=r"(r0), "=r"(r1), "=r"(r2), "=r"(r3) : "r"(a));
}
__device__ __forceinline__ void ldsm4t(uint32_t a, uint32_t& r0, uint32_t& r1,
                                       uint32_t& r2, uint32_t& r3) {
    asm volatile("ldmatrix.sync.aligned.m8n8.x4.trans.shared.b16 {%0,%1,%2,%3}, [%4];"
                 : "=r"(r0), "=r"(r1), "=r"(r2), "=r"(r3) : "r"(a));
}
__device__ __forceinline__ void mma_f16(float* c, const uint32_t* a,
                                        uint32_t b0, uint32_t b1) {
    asm volatile(
        "mma.sync.aligned.m16n8k16.row.col.f32.f16.f16.f32 "
        "{%0,%1,%2,%3}, {%4,%5,%6,%7}, {%8,%9}, {%0,%1,%2,%3};"
        : "+f"(c[0]), "+f"(c[1]), "+f"(c[2]), "+f"(c[3])
        : "r"(a[0]), "r"(a[1]), "r"(a[2]), "r"(a[3]), "r"(b0), "r"(b1));
}
__device__ __forceinline__ void cpasync16(uint32_t dst, const void* src) {
    asm volatile("cp.async.cg.shared.global [%0], [%1], 16;"
                 :: "r"(dst), "l"(src) : "memory");
}
__device__ __forceinline__ void cpasync4(uint32_t dst, const void* src) {
    asm volatile("cp.async.ca.shared.global [%0], [%1], 4;"
                 :: "r"(dst), "l"(src) : "memory");
}
__device__ __forceinline__ void cp_commit() {
    asm volatile("cp.async.commit_group;" ::: "memory");
}
__device__ __forceinline__ void cp_wait1() {
    asm volatile("cp.async.wait_group 1;" ::: "memory");
}
__device__ __forceinline__ void cp_wait0() {
    asm volatile("cp.async.wait_group 0;" ::: "memory");
}
__device__ __forceinline__ void stg_cs2(float* p, float a, float b) {
    asm volatile("st.global.cs.v2.f32 [%0], {%1, %2};"
                 :: "l"(p), "f"(a), "f"(b) : "memory");
}
__device__ __forceinline__ uint32_t pack_h2(float a, float b) {
    __half ha = __float2half_rn(a), hb = __float2half_rn(b);
    return (uint32_t)*(uint16_t*)&ha | ((uint32_t)*(uint16_t*)&hb << 16);
}

// ---------------------------------------------------------------------------
// fused prep: blocks [0,25088) pack x -> g_xh and shifted g_xh2;
//             [25088,25664) split A (identical to R12/R14)
// ---------------------------------------------------------------------------
__global__ void prep_all(const float* __restrict__ x, const float* __restrict__ w) {
    const int b = blockIdx.x;
    if (b < 25088) {
        int i = b * 256 + threadIdx.x;               // 6422528 total
        float4 v = ((const float4*)x)[i];
        float nxt = (4 * i + 4 < XN) ? x[4 * i + 4] : 0.0f;
        ((uint2*)g_xh )[i] = make_uint2(pack_h2(v.x, v.y), pack_h2(v.z, v.w));
        ((uint2*)g_xh2)[i] = make_uint2(pack_h2(v.y, v.z), pack_h2(v.w, nxt));
    } else {
        int i = (b - 25088) * 256 + threadIdx.x;     // 147456 total
        int co = i / 288;
        int r  = i - co * 288;
        int ch = r >> 2, kq = r & 3;
        const float4* p = (const float4*)(w + (size_t)co * KTOT + ch * 32 + kq * 8);
        float4 v0 = p[0], v1 = p[1];
        uint32_t h0 = pack_h2(v0.x * 64.f, v0.y * 64.f);
        uint32_t h1 = pack_h2(v0.z * 64.f, v0.w * 64.f);
        uint32_t h2 = pack_h2(v1.x * 64.f, v1.y * 64.f);
        uint32_t h3 = pack_h2(v1.z * 64.f, v1.w * 64.f);
        int m = co & 127;
        size_t base = ((size_t)(co >> 7) * KCH + ch) * A_TILE
                    + m * 64 + (((uint32_t)kq * 16) ^ ((((uint32_t)m >> 1) & 3) << 4));
        *(uint4*)(g_asplit + base) = make_uint4(h0, h1, h2, h3);
    }
}

// ---------------------------------------------------------------------------
// issue one chunk's copies (A 2x16B cp.async + B 8x4B cp.async), one group.
// B: thread -> rowpair p (rows 2p,2p+1), kslot; dst offsets precomputed.
// ---------------------------------------------------------------------------
__device__ __forceinline__ void issue_chunk(
    int ch, uint32_t stage,
    const unsigned char* aBase, uint32_t aOff,
    const __half* xb, const __half* xb2,
    uint32_t koffs, int kslot, const uint32_t (&dB)[8])
{
    const unsigned char* aSrc = aBase + (size_t)ch * A_TILE;
    cpasync16(stage + aOff,      aSrc);
    cpasync16(stage + aOff + 16, aSrc + 16);

    const uint32_t kb4 = koffs + (uint32_t)(ch * 32 + kslot * 8) * 4;
    uint32_t kk[8];
    asm volatile("ld.shared.v4.b32 {%0,%1,%2,%3}, [%4];"
                 : "=r"(kk[0]), "=r"(kk[1]), "=r"(kk[2]), "=r"(kk[3])
                 : "r"(kb4));
    asm volatile("ld.shared.v4.b32 {%0,%1,%2,%3}, [%4];"
                 : "=r"(kk[4]), "=r"(kk[5]), "=r"(kk[6]), "=r"(kk[7])
                 : "r"(kb4 + 16));
    #pragma unroll
    for (int g = 0; g < 8; ++g) {
        uint32_t ko = kk[g];
        const __half* base = (ko & 1) ? xb2 : xb;
        cpasync4(stage + dB[g], base + (ko & ~1u));
    }
}

// ---------------------------------------------------------------------------
// MMA consumer on one 32-k chunk (identical to R14).
// ---------------------------------------------------------------------------
__device__ __forceinline__ void mma_chunk(
    uint32_t bufb, float (&acc)[4][4][4],
    uint32_t aRowOff, uint32_t aKext, uint32_t aSwz,
    uint32_t bOff1, uint32_t bOff2)
{
    #pragma unroll
    for (int kb = 0; kb < 2; ++kb) {
        const uint32_t aK = ((uint32_t)kb * 32 + aKext) ^ aSwz;
        const uint32_t bBase = bufb + OFF_B + (uint32_t)kb * 4096;

        uint32_t bh[8];
        ldsm4t(bBase + bOff1, bh[0], bh[1], bh[2], bh[3]);
        ldsm4t(bBase + bOff2, bh[4], bh[5], bh[6], bh[7]);

        uint32_t a[16];
        const uint32_t aAddr = bufb + aRowOff + aK;
        #pragma unroll
        for (int am = 0; am < 4; ++am)
            ldsm4(aAddr + am * 1024, a[4*am], a[4*am+1], a[4*am+2], a[4*am+3]);

        #pragma unroll
        for (int am = 0; am < 4; ++am)
            #pragma unroll
            for (int an = 0; an < 4; ++an)
                mma_f16(acc[am][an], a + 4*am, bh[2*an], bh[2*an+1]);
    }
}

// ---------------------------------------------------------------------------
__global__ void __launch_bounds__(256, 2)
conv_mma_kernel(float* __restrict__ out)
{
    extern __shared__ char smem[];
    const uint32_t sb = smem_u32(smem);
    const int tid = threadIdx.x;
    const int bm = blockIdx.x;        // 0..3, fastest -> x gathers shared in L2
    const int bn = blockIdx.y;        // 0..728

    // im2col k -> x-offset table (element offsets)
    for (int k = tid; k < KTOT; k += 256) {
        int ci = k / 9, r9 = k - ci * 9;
        int kh = r9 / 3, kw = r9 - kh * 3;
        *(uint32_t*)(smem + OFF_KOFF + k * 4) = (uint32_t)(ci * 3136 + kh * 56 + kw);
    }

    // A copy: 32B per thread per chunk
    const unsigned char* aBase = g_asplit + (size_t)bm * KCH * A_TILE
                               + (size_t)tid * 32;
    const uint32_t aOff = (uint32_t)tid * 32;

    // B producer invariants (rowpair mapping) + precomputed dst offsets
    const int p = tid & 63, kslot = tid >> 6;
    const int ng = bn * 128 + 2 * p;                 // even
    const int bimg = ng / NPIMG;
    const int prem = ng - bimg * NPIMG;
    const int oh = prem / 54, ow = prem - oh * 54;
    const size_t idx0 = (size_t)bimg * XIMG + oh * 56 + ow;
    const __half* xb  = g_xh  + idx0;
    const __half* xb2 = g_xh2 + idx0;
    const uint32_t koffs = sb + OFF_KOFF;
    uint32_t dB[8];
    {
        const uint32_t np = (uint32_t)p * 4;
        #pragma unroll
        for (int g = 0; g < 8; ++g)
            dB[g] = OFF_B + (uint32_t)kslot * 2048 + (uint32_t)g * 256
                  + (np ^ ((uint32_t)g << 4));
    }

    // MMA invariants: warp grid 2(m) x 4(n)
    const int lane = tid & 31, wid = tid >> 5;
    const int wm = wid & 1, wn = wid >> 1;
    const uint32_t aRowOff = (uint32_t)(wm * 64 + (lane & 15)) * 64;
    const uint32_t aKext   = (uint32_t)(lane >> 4) << 4;
    const uint32_t aSwz    = (uint32_t)(((lane & 15) >> 1) & 3) << 4;
    const int li = lane & 7, lgrp = lane >> 3;
    const int kLoc = li + ((lgrp & 1) << 3);
    const int nn1 = wn * 32 + ((lgrp >> 1) << 3);
    const uint32_t bOff1 = (uint32_t)kLoc * 256
                         + (((uint32_t)(2 * nn1))        ^ ((uint32_t)li << 4));
    const uint32_t bOff2 = (uint32_t)kLoc * 256
                         + (((uint32_t)(2 * (nn1 + 16))) ^ ((uint32_t)li << 4));

    float acc[4][4][4];
    #pragma unroll
    for (int i = 0; i < 4; ++i)
        #pragma unroll
        for (int j = 0; j < 4; ++j)
            #pragma unroll
            for (int r = 0; r < 4; ++r) acc[i][j][r] = 0.0f;

    __syncthreads();                      // koff table ready

    // prologue: groups 0 and 1 into stages 0, 1
    issue_chunk(0, sb,               aBase, aOff, xb, xb2, koffs, kslot, dB);
    cp_commit();
    issue_chunk(1, sb + STAGE_BYTES, aBase, aOff, xb, xb2, koffs, kslot, dB);
    cp_commit();

    int stage = 0;
    for (int ch = 0; ch < KCH; ++ch) {
        cp_wait1();                        // group ch complete
        __syncthreads();                   // visibility + WAR (MMA ch-1 done)
        if (ch + 2 < KCH) {
            int s2 = stage + 2;
            if (s2 >= NSTAGE) s2 -= NSTAGE;
            issue_chunk(ch + 2, sb + (uint32_t)s2 * STAGE_BYTES,
                        aBase, aOff, xb, xb2, koffs, kslot, dB);
        }
        cp_commit();                       // exactly one group per iter

        mma_chunk(sb + (uint32_t)stage * STAGE_BYTES, acc,
                  aRowOff, aKext, aSwz, bOff1, bOff2);

        if (++stage == NSTAGE) stage = 0;
    }

    // epilogue: scale by 1/64; streaming stores (evict-first)
    const float s = 0.015625f;
    const int lane4 = lane >> 2, lane2 = (lane & 3) * 2;
    #pragma unroll
    for (int an = 0; an < 4; ++an) {
        const int gn = bn * 128 + wn * 32 + an * 8 + lane2;
        const int b2 = gn / NPIMG;
        const int r2 = gn - b2 * NPIMG;
        float* op = out + (size_t)b2 * OUTIMG + r2;
        #pragma unroll
        for (int am = 0; am < 4; ++am) {
            const int co = bm * 128 + wm * 64 + am * 16 + lane4;
            stg_cs2(op + (size_t)co * NPIMG,
                    acc[am][an][0] * s, acc[am][an][1] * s);
            stg_cs2(op + (size_t)(co + 8) * NPIMG,
                    acc[am][an][2] * s, acc[am][an][3] * s);
        }
    }
}

// ---------------------------------------------------------------------------
extern "C" void kernel_launch(void* const* d_in, const int* in_sizes, int n_in,
                              void* d_out, int out_size)
{
    const float* x = (const float*)d_in[0];   // [32,256,56,56]
    const float* w = (const float*)d_in[1];   // [512,256,3,3]
    float* out = (float*)d_out;               // [32,512,54,54]

    cudaFuncSetAttribute(conv_mma_kernel,
                         cudaFuncAttributeMaxDynamicSharedMemorySize, SMEM_BYTES);

    prep_all<<<25664, 256>>>(x, w);           // pack x (+shifted copy) + split A
    conv_mma_kernel<<<dim3(4, 729), 256, SMEM_BYTES>>>(out);
}

// round 16
// speedup vs baseline: 1.0823x; 1.0823x over previous
#include <cuda_runtime.h>
#include <cuda_fp16.h>
#include <cstdint>

// ============================================================================
// Single-term fp16 mma.sync implicit-GEMM conv, round 16 (= R14 champion +
// pre-biased gather offsets).
// D = ah*bh ; A = w*64 fp16 (epilogue * 1/64), B = x fp16, rel_err ~2.9e-4.
// B path: row-pair LDG.32 gathers from combined buffer g_x2 = [x | x-shifted];
// im2col table stores FINAL byte offsets (parity fold done once at init),
// so each gather is one IADD + one LDG.32. k-major swizzled B smem +
// ldsm.trans. Pipeline: LDG_B(ch+1) -> cp.async_A(ch+1) -> MMA(ch) -> STS.
// ============================================================================

#define KTOT   2304
#define KCH    72            // 2304 / 32
#define NPIMG  2916
#define OUTIMG (512*NPIMG)
#define XIMG   (256*3136)
#define XN     (32*XIMG)     // 25690112 elements

#define A_TILE      8192     // A plane, 128 rows x 64B (swizzled)
#define STAGE_BYTES 16384    // A 8KB + B 8KB
#define OFF_B       8192
#define OFF_KOFF    32768                  // after 2 stages
#define SMEM_BYTES  (OFF_KOFF + KTOT*4)    // 41984

// A (scaled x64, fp16) in swizzled smem-tile layout: [mt(4)][ch(72)][8KB]
__device__ __align__(16) unsigned char g_asplit[4ull*72*8192];    // 2.4MB
// combined x buffer: [0,XN) = x as fp16 ; [XN,2XN) = shifted copy x[j+1]
__device__ __align__(16) __half g_x2[2ull*XN];                    // 103MB

// ---------------------------------------------------------------------------
__device__ __forceinline__ uint32_t smem_u32(const void* p) {
    uint32_t a;
    asm("{ .reg .u64 t; cvta.to.shared.u64 t, %1; cvt.u32.u64 %0, t; }"
        : "=r"(a) : "l"(p));
    return a;
}
__device__ __forceinline__ void sts32(uint32_t addr, uint32_t v) {
    asm volatile("st.shared.b32 [%0], %1;" :: "r"(addr), "r"(v));
}
__device__ __forceinline__ void ldsm4(uint32_t a, uint32_t& r0, uint32_t& r1,
                                      uint32_t& r2, uint32_t& r3) {
    asm volatile("ldmatrix.sync.aligned.m8n8.x4.shared.b16 {%0,%1,%2,%3}, [%4];"
                 : "=r"(r0), "=r"(r1), "=r"(r2), "=r"(r3) : "r"(a));
}
__device__ __forceinline__ void ldsm4t(uint32_t a, uint32_t& r0, uint32_t& r1,
                                       uint32_t& r2, uint32_t& r3) {
    asm volatile("ldmatrix.sync.aligned.m8n8.x4.trans.shared.b16 {%0,%1,%2,%3}, [%4];"
                 : "=r"(r0), "=r"(r1), "=r"(r2), "=r"(r3) : "r"(a));
}
__device__ __forceinline__ void mma_f16(float* c, const uint32_t* a,
                                        uint32_t b0, uint32_t b1) {
    asm volatile(
        "mma.sync.aligned.m16n8k16.row.col.f32.f16.f16.f32 "
        "{%0,%1,%2,%3}, {%4,%5,%6,%7}, {%8,%9}, {%0,%1,%2,%3};"
        : "+f"(c[0]), "+f"(c[1]), "+f"(c[2]), "+f"(c[3])
        : "r"(a[0]), "r"(a[1]), "r"(a[2]), "r"(a[3]), "r"(b0), "r"(b1));
}
__device__ __forceinline__ void cpasync16(uint32_t dst, const void* src) {
    asm volatile("cp.async.cg.shared.global [%0], [%1], 16;"
                 :: "r"(dst), "l"(src) : "memory");
}
__device__ __forceinline__ void cp_commit() {
    asm volatile("cp.async.commit_group;" ::: "memory");
}
__device__ __forceinline__ void cp_wait0() {
    asm volatile("cp.async.wait_group 0;" ::: "memory");
}
__device__ __forceinline__ uint32_t ldg32(const void* p) {
    uint32_t v;
    asm volatile("ld.global.nc.u32 %0, [%1];" : "=r"(v) : "l"(p));
    return v;
}
__device__ __forceinline__ void stg_cs2(float* p, float a, float b) {
    asm volatile("st.global.cs.v2.f32 [%0], {%1, %2};"
                 :: "l"(p), "f"(a), "f"(b) : "memory");
}
__device__ __forceinline__ uint32_t pack_h2(float a, float b) {
    __half ha = __float2half_rn(a), hb = __float2half_rn(b);
    return (uint32_t)*(uint16_t*)&ha | ((uint32_t)*(uint16_t*)&hb << 16);
}

// ---------------------------------------------------------------------------
// fused prep: blocks [0,25088) pack x into both halves of g_x2;
//             [25088,25664) split A
// ---------------------------------------------------------------------------
__global__ void prep_all(const float* __restrict__ x, const float* __restrict__ w) {
    const int b = blockIdx.x;
    if (b < 25088) {
        int i = b * 256 + threadIdx.x;               // 6422528 total
        float4 v = ((const float4*)x)[i];
        float nxt = (4 * i + 4 < XN) ? x[4 * i + 4] : 0.0f;
        ((uint2*)g_x2)[i] = make_uint2(pack_h2(v.x, v.y), pack_h2(v.z, v.w));
        ((uint2*)(g_x2 + XN))[i] = make_uint2(pack_h2(v.y, v.z), pack_h2(v.w, nxt));
    } else {
        int i = (b - 25088) * 256 + threadIdx.x;     // 147456 total
        int co = i / 288;
        int r  = i - co * 288;
        int ch = r >> 2, kq = r & 3;
        const float4* p = (const float4*)(w + (size_t)co * KTOT + ch * 32 + kq * 8);
        float4 v0 = p[0], v1 = p[1];
        uint32_t h0 = pack_h2(v0.x * 64.f, v0.y * 64.f);
        uint32_t h1 = pack_h2(v0.z * 64.f, v0.w * 64.f);
        uint32_t h2 = pack_h2(v1.x * 64.f, v1.y * 64.f);
        uint32_t h3 = pack_h2(v1.z * 64.f, v1.w * 64.f);
        int m = co & 127;
        size_t base = ((size_t)(co >> 7) * KCH + ch) * A_TILE
                    + m * 64 + (((uint32_t)kq * 16) ^ ((((uint32_t)m >> 1) & 3) << 4));
        *(uint4*)(g_asplit + base) = make_uint4(h0, h1, h2, h3);
    }
}

// ---------------------------------------------------------------------------
// B producer: thread -> rowpair p (rows 2p,2p+1), kslot = tid>>6.
// Table holds final byte offsets; gather = base + offset, LDG.32.
// ---------------------------------------------------------------------------
__device__ __forceinline__ void load_b(
    int ch, const char* xbyte, uint32_t koffs, int kslot, uint32_t (&bx)[8])
{
    const uint32_t kb4 = koffs + (uint32_t)(ch * 32 + kslot * 8) * 4;
    uint32_t kk[8];
    asm volatile("ld.shared.v4.b32 {%0,%1,%2,%3}, [%4];"
                 : "=r"(kk[0]), "=r"(kk[1]), "=r"(kk[2]), "=r"(kk[3])
                 : "r"(kb4));
    asm volatile("ld.shared.v4.b32 {%0,%1,%2,%3}, [%4];"
                 : "=r"(kk[4]), "=r"(kk[5]), "=r"(kk[6]), "=r"(kk[7])
                 : "r"(kb4 + 16));
    #pragma unroll
    for (int g = 0; g < 8; ++g)
        bx[g] = ldg32(xbyte + kk[g]);
}
__device__ __forceinline__ void store_b(
    uint32_t bufb, const uint32_t (&bx)[8], int p, int kslot)
{
    const uint32_t sB = bufb + OFF_B + (uint32_t)kslot * 2048;
    const uint32_t np = (uint32_t)p * 4;
    #pragma unroll
    for (int g = 0; g < 8; ++g)
        sts32(sB + (uint32_t)g * 256 + (np ^ ((uint32_t)g << 4)), bx[g]);
}

// ---------------------------------------------------------------------------
// MMA consumer on one 32-k chunk (identical to R14). buf: [A 0][B 8K]
// ---------------------------------------------------------------------------
__device__ __forceinline__ void mma_chunk(
    uint32_t bufb, float (&acc)[4][4][4],
    uint32_t aRowOff, uint32_t aKext, uint32_t aSwz,
    uint32_t bOff1, uint32_t bOff2)
{
    #pragma unroll
    for (int kb = 0; kb < 2; ++kb) {
        const uint32_t aK = ((uint32_t)kb * 32 + aKext) ^ aSwz;
        const uint32_t bBase = bufb + OFF_B + (uint32_t)kb * 4096;

        uint32_t bh[8];
        ldsm4t(bBase + bOff1, bh[0], bh[1], bh[2], bh[3]);
        ldsm4t(bBase + bOff2, bh[4], bh[5], bh[6], bh[7]);

        uint32_t a[16];
        const uint32_t aAddr = bufb + aRowOff + aK;
        #pragma unroll
        for (int am = 0; am < 4; ++am)
            ldsm4(aAddr + am * 1024, a[4*am], a[4*am+1], a[4*am+2], a[4*am+3]);

        #pragma unroll
        for (int am = 0; am < 4; ++am)
            #pragma unroll
            for (int an = 0; an < 4; ++an)
                mma_f16(acc[am][an], a + 4*am, bh[2*an], bh[2*an+1]);
    }
}

// ---------------------------------------------------------------------------
__global__ void __launch_bounds__(256, 2)
conv_mma_kernel(float* __restrict__ out)
{
    extern __shared__ char smem[];
    const uint32_t sb = smem_u32(smem);
    const int tid = threadIdx.x;
    const int bm = blockIdx.x;        // 0..3, fastest -> x gathers shared in L2
    const int bn = blockIdx.y;        // 0..728

    // im2col k -> FINAL byte offset into g_x2 (parity folded once here):
    //   e = odd(ko) ? XN + ko - 1 : ko ; store 2*e
    for (int k = tid; k < KTOT; k += 256) {
        int ci = k / 9, r9 = k - ci * 9;
        int kh = r9 / 3, kw = r9 - kh * 3;
        uint32_t ko = (uint32_t)(ci * 3136 + kh * 56 + kw);
        uint32_t e = (ko & 1) ? ((uint32_t)XN + ko - 1) : ko;
        *(uint32_t*)(smem + OFF_KOFF + k * 4) = e * 2;
    }

    // A copy: 32B per thread per chunk
    const unsigned char* aBase = g_asplit + (size_t)bm * KCH * A_TILE
                               + (size_t)tid * 32;
    const uint32_t aOff = (uint32_t)tid * 32;

    // B producer invariants (rowpair mapping)
    const int p = tid & 63, kslot = tid >> 6;
    const int ng = bn * 128 + 2 * p;                 // even
    const int bimg = ng / NPIMG;
    const int prem = ng - bimg * NPIMG;
    const int oh = prem / 54, ow = prem - oh * 54;
    const size_t idx0 = (size_t)bimg * XIMG + oh * 56 + ow;
    const char* xbyte = (const char*)g_x2 + idx0 * 2;
    const uint32_t koffs = sb + OFF_KOFF;

    // MMA invariants: warp grid 2(m) x 4(n)
    const int lane = tid & 31, wid = tid >> 5;
    const int wm = wid & 1, wn = wid >> 1;
    const uint32_t aRowOff = (uint32_t)(wm * 64 + (lane & 15)) * 64;
    const uint32_t aKext   = (uint32_t)(lane >> 4) << 4;
    const uint32_t aSwz    = (uint32_t)(((lane & 15) >> 1) & 3) << 4;
    const int li = lane & 7, lgrp = lane >> 3;
    const int kLoc = li + ((lgrp & 1) << 3);
    const int nn1 = wn * 32 + ((lgrp >> 1) << 3);
    const uint32_t bOff1 = (uint32_t)kLoc * 256
                         + (((uint32_t)(2 * nn1))        ^ ((uint32_t)li << 4));
    const uint32_t bOff2 = (uint32_t)kLoc * 256
                         + (((uint32_t)(2 * (nn1 + 16))) ^ ((uint32_t)li << 4));

    float acc[4][4][4];
    #pragma unroll
    for (int i = 0; i < 4; ++i)
        #pragma unroll
        for (int j = 0; j < 4; ++j)
            #pragma unroll
            for (int r = 0; r < 4; ++r) acc[i][j][r] = 0.0f;

    __syncthreads();                      // koff table ready

    // prologue: stage 0
    cpasync16(sb + aOff,      aBase);
    cpasync16(sb + aOff + 16, aBase + 16);
    cp_commit();
    {
        uint32_t bx0[8];
        load_b(0, xbyte, koffs, kslot, bx0);
        store_b(sb, bx0, p, kslot);
    }
    cp_wait0();
    __syncthreads();

    for (int ch = 0; ch < KCH; ++ch) {
        const uint32_t cur = sb + (uint32_t)(ch & 1) * STAGE_BYTES;
        const uint32_t nxt = sb + (uint32_t)((ch + 1) & 1) * STAGE_BYTES;
        const bool pre = (ch + 1 < KCH);

        uint32_t bx[8];
        if (pre) {
            load_b(ch + 1, xbyte, koffs, kslot, bx);     // LDGs issue, no wait
            const unsigned char* aSrc = aBase + (size_t)(ch + 1) * A_TILE;
            cpasync16(nxt + aOff,      aSrc);
            cpasync16(nxt + aOff + 16, aSrc + 16);
            cp_commit();
        }

        mma_chunk(cur, acc, aRowOff, aKext, aSwz, bOff1, bOff2);

        if (pre)
            store_b(nxt, bx, p, kslot);                  // LDGs landed during MMA
        cp_wait0();
        __syncthreads();
    }

    // epilogue: scale by 1/64; streaming stores (evict-first)
    const float s = 0.015625f;
    const int lane4 = lane >> 2, lane2 = (lane & 3) * 2;
    #pragma unroll
    for (int an = 0; an < 4; ++an) {
        const int gn = bn * 128 + wn * 32 + an * 8 + lane2;
        const int b2 = gn / NPIMG;
        const int r2 = gn - b2 * NPIMG;
        float* op = out + (size_t)b2 * OUTIMG + r2;
        #pragma unroll
        for (int am = 0; am < 4; ++am) {
            const int co = bm * 128 + wm * 64 + am * 16 + lane4;
            stg_cs2(op + (size_t)co * NPIMG,
                    acc[am][an][0] * s, acc[am][an][1] * s);
            stg_cs2(op + (size_t)(co + 8) * NPIMG,
                    acc[am][an][2] * s, acc[am][an][3] * s);
        }
    }
}

// ---------------------------------------------------------------------------
extern "C" void kernel_launch(void* const* d_in, const int* in_sizes, int n_in,
                              void* d_out, int out_size)
{
    const float* x = (const float*)d_in[0];   // [32,256,56,56]
    const float* w = (const float*)d_in[1];   // [512,256,3,3]
    float* out = (float*)d_out;               // [32,512,54,54]

    cudaFuncSetAttribute(conv_mma_kernel,
                         cudaFuncAttributeMaxDynamicSharedMemorySize, SMEM_BYTES);

    prep_all<<<25664, 256>>>(x, w);           // pack x (both halves) + split A
    conv_mma_kernel<<<dim3(4, 729), 256, SMEM_BYTES>>>(out);
}